// round 14
// baseline (speedup 1.0000x reference)
#include <cuda_runtime.h>
#include <cuda_fp16.h>
#include <cstdint>

#define NTHREADS 256
#define TM 32

__constant__ float c_HA[6][5] = {
    {0.f, 0.f, 0.f, 0.f, 0.f},
    {0.05f, 0.f, 0.f, 0.f, 0.f},
    {0.01875f, 0.05625f, 0.f, 0.f, 0.f},
    {0.24444444444444444f, -0.93333333333333333f, 0.88888888888888888f, 0.f, 0.f},
    {0.73814967232162782f, -2.89894833155005335f, 2.45572321290182902f, -0.07270233196159122f, 0.f},
    {0.71156881313131313f, -2.68939393939393939f, 2.22660567943586826f, 0.06960227272727273f, -0.06838282589193830f}
};
__constant__ float c_HB[6] = {
    0.02278645833333333f, 0.f, 0.11230907457322552f,
    0.16276041666666666f, -0.08059404481132076f, 0.03273809523809524f
};

__device__ __align__(16) __half g_Wp1[256 * 64];
__device__ __align__(16) __half g_Wp2[256 * 256];
__device__ __align__(16) __half g_Wp3[256 * 256];
__device__ __align__(16) __half g_Wp4[64 * 256];
__device__ __align__(16) __half g_Wp4t[256 * 64];         // W4^T (for V = W4^T eps)
__device__ __align__(16) uint32_t g_U1[1024 * 256 * 16];  // per-(cta,warp,lane) U1 frags

// ---- SMEM layout ----
#define XLD 144
#define SM_XA    0              // [256][72h] = 36864
#define SM_XB    36864          // [256][72h]; rows 0..63 double as X0 (fwd only)
#define SM_X0    SM_XB
#define SM_KDZ   73728          // fp16 [5][64][34] = 21760
#define SM_ZB    95488          // f32 [64][33] = 8448
#define SM_EP    103936         // fp16 [64][34] = 4352
#define SM_BIAS  108288         // fp16 832 -> 1664
#define SM_RED   109952         // f32 [8][32] = 1024
#define SM_LPT   110976         // f32 [32] = 128
#define SM_TOTAL 111104

#define KDZP 34
#define KDZS 2176
#define ZBP  33
#define EPP  34

__device__ __forceinline__ uint32_t smem_u32(const void* p) {
    uint32_t a;
    asm("{ .reg .u64 t; cvta.to.shared.u64 t, %1; cvt.u32.u64 %0, t; }" : "=r"(a) : "l"(p));
    return a;
}
__device__ __forceinline__ void ldsm4t(uint32_t addr, uint32_t& r0, uint32_t& r1,
                                       uint32_t& r2, uint32_t& r3) {
    asm volatile("ldmatrix.sync.aligned.m8n8.x4.trans.shared.b16 {%0,%1,%2,%3}, [%4];"
                 : "=r"(r0), "=r"(r1), "=r"(r2), "=r"(r3) : "r"(addr));
}
__device__ __forceinline__ void mma16816h(uint32_t* c, const uint4& a, uint32_t b0, uint32_t b1) {
    asm volatile("mma.sync.aligned.m16n8k16.row.col.f16.f16.f16.f16 "
                 "{%0,%1}, {%2,%3,%4,%5}, {%6,%7}, {%0,%1};"
                 : "+r"(c[0]), "+r"(c[1])
                 : "r"(a.x), "r"(a.y), "r"(a.z), "r"(a.w), "r"(b0), "r"(b1));
}
__device__ __forceinline__ float tanh_fast(float x) {
    float e;
    asm("ex2.approx.f32 %0, %1;" : "=f"(e) : "f"(x * 2.8853900817779268f));
    float q = e + 1.0f;
    float r = __int_as_float(0x7EF311C3 - __float_as_int(q));
    r = r * fmaf(-q, r, 2.f);
    r = r * fmaf(-q, r, 2.f);
    return fmaf(-2.0f, r, 1.0f);
}

// ---- prep: pack fp32 weights into fp16 fragment-major layouts ----
__global__ void prep_kernel(const float* __restrict__ W1, const float* __restrict__ W2,
                            const float* __restrict__ W3, const float* __restrict__ W4)
{
    int t = blockIdx.x * blockDim.x + threadIdx.x;
    if (t >= 704 * 32) return;
    int frag = t >> 5, lane = t & 31;
    int g = lane >> 2, j2 = (lane & 3) * 2;
    __half h[8];
    if (frag >= 640) {               // W4^T: [256][64]
        int fl = frag - 640;
        int mt = fl >> 2, ks = fl & 3;
        int r0 = mt * 16 + g, r1 = r0 + 8;
        int c0 = ks * 16 + j2;
        h[0] = __float2half_rn(W4[(c0)     * 256 + r0]);
        h[1] = __float2half_rn(W4[(c0 + 1) * 256 + r0]);
        h[2] = __float2half_rn(W4[(c0)     * 256 + r1]);
        h[3] = __float2half_rn(W4[(c0 + 1) * 256 + r1]);
        h[4] = __float2half_rn(W4[(c0 + 8) * 256 + r0]);
        h[5] = __float2half_rn(W4[(c0 + 9) * 256 + r0]);
        h[6] = __float2half_rn(W4[(c0 + 8) * 256 + r1]);
        h[7] = __float2half_rn(W4[(c0 + 9) * 256 + r1]);
        *(uint4*)(g_Wp4t + fl * 256 + lane * 8) = *(uint4*)h;
        return;
    }
    const float* W; __half* dst; int ksn, ld, fl;
    if (frag < 64)       { W = W1; dst = g_Wp1; ksn = 4;  ld = 64;  fl = frag; }
    else if (frag < 320) { W = W2; dst = g_Wp2; ksn = 16; ld = 256; fl = frag - 64; }
    else if (frag < 576) { W = W3; dst = g_Wp3; ksn = 16; ld = 256; fl = frag - 320; }
    else                 { W = W4; dst = g_Wp4; ksn = 16; ld = 256; fl = frag - 576; }
    int mt = fl / ksn, ks = fl % ksn;
    int r0 = mt * 16 + g, r1 = r0 + 8;
    int c0 = ks * 16 + j2;
    h[0] = __float2half_rn(W[r0 * ld + c0]);
    h[1] = __float2half_rn(W[r0 * ld + c0 + 1]);
    h[2] = __float2half_rn(W[r1 * ld + c0]);
    h[3] = __float2half_rn(W[r1 * ld + c0 + 1]);
    h[4] = __float2half_rn(W[r0 * ld + c0 + 8]);
    h[5] = __float2half_rn(W[r0 * ld + c0 + 9]);
    h[6] = __float2half_rn(W[r1 * ld + c0 + 8]);
    h[7] = __float2half_rn(W[r1 * ld + c0 + 9]);
    *(uint4*)(dst + fl * 256 + lane * 8) = *(uint4*)h;
}

template<int KSTEPS, int MT>
__device__ __forceinline__ void wpre(const uint4* __restrict__ wf, int lane, uint4* an)
{
#pragma unroll
    for (int mt = 0; mt < MT; mt++) {
        an[mt]      = wf[mt * KSTEPS * 32 + lane];
        an[MT + mt] = wf[(mt * KSTEPS + 1) * 32 + lane];
    }
}

// ---- software-pipelined tensor-core GEMM (fp16 acc) ----
template<int KSTEPS, int NPH, int MT>
__device__ __forceinline__ void gemm_pipe(const uint4* __restrict__ wf,
                                          uint32_t xaddr, int lane,
                                          uint32_t* acc, uint4* an)
{
#pragma unroll
    for (int i = 0; i < MT * NPH * 8; i++) acc[i] = 0u;
    uint32_t bb[2][8];
    ldsm4t(xaddr,      bb[0][0], bb[0][1], bb[0][2], bb[0][3]);
    ldsm4t(xaddr + 32, bb[0][4], bb[0][5], bb[0][6], bb[0][7]);
    int par = 0;
#pragma unroll
    for (int ks = 0; ks < KSTEPS; ks++) {
        uint4 ac[MT];
#pragma unroll
        for (int mt = 0; mt < MT; mt++) ac[mt] = an[(ks & 1) * MT + mt];
        if (ks + 2 < KSTEPS) {
#pragma unroll
            for (int mt = 0; mt < MT; mt++)
                an[(ks & 1) * MT + mt] = wf[(mt * KSTEPS + ks + 2) * 32 + lane];
        }
#pragma unroll
        for (int h = 0; h < NPH; h++) {
            int nh = h + 1, nks = ks;
            if (nh == NPH) { nh = 0; nks = ks + 1; }
            if (nks < KSTEPS) {
                uint32_t a2 = xaddr + nks * (16 * XLD) + nh * 64;
                ldsm4t(a2,      bb[par ^ 1][0], bb[par ^ 1][1], bb[par ^ 1][2], bb[par ^ 1][3]);
                ldsm4t(a2 + 32, bb[par ^ 1][4], bb[par ^ 1][5], bb[par ^ 1][6], bb[par ^ 1][7]);
            }
            const uint32_t* B = bb[par];
#pragma unroll
            for (int mt = 0; mt < MT; mt++) {
                uint32_t* am = acc + mt * NPH * 8 + 8 * h;
                mma16816h(am + 0, ac[mt], B[0], B[1]);
                mma16816h(am + 2, ac[mt], B[2], B[3]);
                mma16816h(am + 4, ac[mt], B[4], B[5]);
                mma16816h(am + 6, ac[mt], B[6], B[7]);
            }
            par ^= 1;
        }
    }
}

// ---- L1 epilogue: fwd acc + cached U1 -> tanh + tangent -> XA ----
__device__ __forceinline__ void epi_l1(const uint32_t* acc, const uint32_t* u1r,
                                       char* xout, const __half* bias, int w, int lane)
{
    int g = lane >> 2, j2 = (lane & 3) * 2;
#pragma unroll
    for (int mt = 0; mt < 2; mt++) {
        int r = w * 32 + mt * 16 + g;
        float b0 = __half2float(bias[r]), b8 = __half2float(bias[r + 8]);
        char* row0 = xout + r * XLD;
        char* row8 = row0 + 8 * XLD;
#pragma unroll
        for (int nb = 0; nb < 4; nb++) {
            float2 c01 = __half22float2(*(const __half2*)(acc + mt * 8 + 2 * nb));
            float2 c23 = __half22float2(*(const __half2*)(acc + mt * 8 + 2 * nb + 1));
            float2 u01 = __half22float2(*(const __half2*)(u1r + mt * 8 + 2 * nb));
            float2 u23 = __half22float2(*(const __half2*)(u1r + mt * 8 + 2 * nb + 1));
            int n2 = (nb * 8 + j2) * 2;
            float y0 = tanh_fast(c01.x + b0), y1 = tanh_fast(c01.y + b0);
            float y2 = tanh_fast(c23.x + b8), y3 = tanh_fast(c23.y + b8);
            *(__half2*)(row0 + n2)      = __floats2half2_rn(y0, y1);
            *(__half2*)(row0 + 64 + n2) = __floats2half2_rn((1.f - y0 * y0) * u01.x,
                                                            (1.f - y1 * y1) * u01.y);
            *(__half2*)(row8 + n2)      = __floats2half2_rn(y2, y3);
            *(__half2*)(row8 + 64 + n2) = __floats2half2_rn((1.f - y2 * y2) * u23.x,
                                                            (1.f - y3 * y3) * u23.y);
        }
    }
}

// ---- hidden epilogue (NPH=2, MT=2). DIV: fold divergence via V regs ----
template<bool DIV>
__device__ __forceinline__ void epi_hidden(const uint32_t* acc, char* xout,
                                           const __half* bias, int w, int lane,
                                           const uint32_t* vreg, float* red)
{
    int g = lane >> 2, j2 = (lane & 3) * 2;
    float ds0[4], ds1[4];
    if (DIV) {
#pragma unroll
        for (int nb = 0; nb < 4; nb++) { ds0[nb] = 0.f; ds1[nb] = 0.f; }
    }
#pragma unroll
    for (int mt = 0; mt < 2; mt++) {
        int r = w * 32 + mt * 16 + g;
        float b0 = __half2float(bias[r]), b8 = __half2float(bias[r + 8]);
        char* row0 = xout + r * XLD;
        char* row8 = row0 + 8 * XLD;
#pragma unroll
        for (int nb = 0; nb < 4; nb++) {
            float2 cf01 = __half22float2(*(const __half2*)(acc + mt * 16 + 2 * nb));
            float2 cf23 = __half22float2(*(const __half2*)(acc + mt * 16 + 2 * nb + 1));
            float2 ct01 = __half22float2(*(const __half2*)(acc + mt * 16 + 8 + 2 * nb));
            float2 ct23 = __half22float2(*(const __half2*)(acc + mt * 16 + 8 + 2 * nb + 1));
            int n2 = (nb * 8 + j2) * 2;
            float y0 = tanh_fast(cf01.x + b0), y1 = tanh_fast(cf01.y + b0);
            float y2 = tanh_fast(cf23.x + b8), y3 = tanh_fast(cf23.y + b8);
            float t0 = (1.f - y0 * y0) * ct01.x, t1 = (1.f - y1 * y1) * ct01.y;
            float t2 = (1.f - y2 * y2) * ct23.x, t3 = (1.f - y3 * y3) * ct23.y;
            *(__half2*)(row0 + n2)      = __floats2half2_rn(y0, y1);
            *(__half2*)(row0 + 64 + n2) = __floats2half2_rn(t0, t1);
            *(__half2*)(row8 + n2)      = __floats2half2_rn(y2, y3);
            *(__half2*)(row8 + 64 + n2) = __floats2half2_rn(t2, t3);
            if (DIV) {
                float2 v01 = __half22float2(*(const __half2*)(vreg + mt * 8 + 2 * nb));
                float2 v23 = __half22float2(*(const __half2*)(vreg + mt * 8 + 2 * nb + 1));
                ds0[nb] += t0 * v01.x + t2 * v23.x;
                ds1[nb] += t1 * v01.y + t3 * v23.y;
            }
        }
    }
    if (DIV) {
#pragma unroll
        for (int mask = 4; mask <= 16; mask <<= 1) {
#pragma unroll
            for (int nb = 0; nb < 4; nb++) {
                ds0[nb] += __shfl_xor_sync(0xffffffffu, ds0[nb], mask);
                ds1[nb] += __shfl_xor_sync(0xffffffffu, ds1[nb], mask);
            }
        }
        if (g == 0) {
#pragma unroll
            for (int nb = 0; nb < 4; nb++) {
                red[w * 32 + nb * 8 + j2]     = ds0[nb];
                red[w * 32 + nb * 8 + j2 + 1] = ds1[nb];
            }
        }
    }
}

// ---- forward-only epilogue (NPH=1), for s==1 ----
__device__ __forceinline__ void epi_fwd(const uint32_t* acc, char* xout,
                                        const __half* bias, int w, int lane)
{
    int g = lane >> 2, j2 = (lane & 3) * 2;
#pragma unroll
    for (int mt = 0; mt < 2; mt++) {
        int r = w * 32 + mt * 16 + g;
        float b0 = __half2float(bias[r]), b8 = __half2float(bias[r + 8]);
        char* row0 = xout + r * XLD;
        char* row8 = row0 + 8 * XLD;
#pragma unroll
        for (int nb = 0; nb < 4; nb++) {
            float2 c01 = __half22float2(*(const __half2*)(acc + mt * 8 + 2 * nb));
            float2 c23 = __half22float2(*(const __half2*)(acc + mt * 8 + 2 * nb + 1));
            int n2 = (nb * 8 + j2) * 2;
            float y0 = tanh_fast(c01.x + b0), y1 = tanh_fast(c01.y + b0);
            float y2 = tanh_fast(c23.x + b8), y3 = tanh_fast(c23.y + b8);
            *(__half2*)(row0 + n2) = __floats2half2_rn(y0, y1);
            *(__half2*)(row8 + n2) = __floats2half2_rn(y2, y3);
        }
    }
}

__global__ void __launch_bounds__(NTHREADS, 2)
cnf_kernel(const float* __restrict__ x, const float* __restrict__ eps,
           const float* __restrict__ b1, const float* __restrict__ b2,
           const float* __restrict__ b3, const float* __restrict__ b4,
           float* __restrict__ out)
{
    extern __shared__ char smc[];
    const uint32_t sbase = smem_u32(smc);
    const int tid = threadIdx.x;
    const int w = tid >> 5;
    const int lane = tid & 31;
    const int mbase = blockIdx.x * TM;

    __half* biash = (__half*)(smc + SM_BIAS);
    char*   x0s   = smc + SM_X0;
    char*   xas   = smc + SM_XA;
    char*   xbs   = smc + SM_XB;
    __half* kdzh  = (__half*)(smc + SM_KDZ);
    float*  zb    = (float*)(smc + SM_ZB);
    __half* eph   = (__half*)(smc + SM_EP);
    float*  red   = (float*)(smc + SM_RED);
    float*  lpT   = (float*)(smc + SM_LPT);
    const __half* b4h = biash + 768;

    const uint4* wp1w  = (const uint4*)g_Wp1  + (w * 2 * 4) * 32;
    const uint4* wp2w  = (const uint4*)g_Wp2  + (w * 2 * 16) * 32;
    const uint4* wp3w  = (const uint4*)g_Wp3  + (w * 2 * 16) * 32;
    const uint4* wp4w  = (const uint4*)g_Wp4  + ((w & 3) * 16) * 32;
    const uint4* wp4tw = (const uint4*)g_Wp4t + (w * 2 * 4) * 32;
    uint4* u1gp = (uint4*)(g_U1 + ((size_t)(blockIdx.x * 8 + w) * 32 + lane) * 16);

    biash[tid]       = __float2half_rn(b1[tid]);
    biash[256 + tid] = __float2half_rn(b2[tid]);
    biash[512 + tid] = __float2half_rn(b3[tid]);
    if (tid < 64) biash[768 + tid] = __float2half_rn(b4[tid]);
    for (int e = tid; e < 64 * TM; e += NTHREADS) {
        int d = e & 63, m = e >> 6;
        float xv = x[(mbase + m) * 64 + d];
        float ev = eps[(mbase + m) * 64 + d];
        __half evh = __float2half_rn(ev);
        zb[d * ZBP + m]  = xv;
        eph[d * EPP + m] = evh;
        *(__half*)(x0s + d * XLD + m * 2) = __float2half_rn(xv);
        *(__half*)(xas + d * XLD + m * 2) = evh;   // eps tile for V / U1 gemms
    }
    if (tid < TM) lpT[tid] = 0.f;
    __syncthreads();

    const uint32_t xpat = ((lane & 7) + ((lane >> 3) & 1) * 8) * XLD + (lane >> 4) * 16;

    // V = W4^T eps (divergence trick) and U1 = W1 eps (stage-constant L1 tangent)
    uint4 an[4];
    uint32_t vreg[16];
    wpre<4, 2>(wp4tw, lane, an);
    gemm_pipe<4, 1, 2>(wp4tw, sbase + SM_XA + xpat, lane, vreg, an);
    {
        uint32_t u1r[16];
        wpre<4, 2>(wp1w, lane, an);
        gemm_pipe<4, 1, 2>(wp1w, sbase + SM_XA + xpat, lane, u1r, an);
        u1gp[0] = *(uint4*)(u1r + 0);
        u1gp[1] = *(uint4*)(u1r + 4);
        u1gp[2] = *(uint4*)(u1r + 8);
        u1gp[3] = *(uint4*)(u1r + 12);
    }
    wpre<4, 2>(wp1w, lane, an);
    __syncthreads();

    // Anti-phase skew: odd CTAs delay ~half a stage so the two co-resident
    // CTAs' GEMM and epilogue windows interleave instead of coinciding.
    if (blockIdx.x & 1) {
        long long t0 = clock64();
        while (clock64() - t0 < 14000) { }
    }
    __syncthreads();

    uint32_t acc[32];
    float pend = 0.f;

#pragma unroll 1
    for (int step = 0; step < 4; step++) {
#pragma unroll 1
        for (int s = 0; s < 6; s++) {
            if (pend != 0.f && tid < 32)
                lpT[tid] -= pend * (red[tid] + red[32 + tid] + red[64 + tid] + red[96 + tid]
                                  + red[128 + tid] + red[160 + tid] + red[192 + tid] + red[224 + tid]);

            // L1: forward-only, tangent from cached U1
            uint32_t u1r[16];
            if (s != 1) {
                uint4 ua = u1gp[0], ub = u1gp[1], uc = u1gp[2], ud = u1gp[3];
                *(uint4*)(u1r + 0) = ua; *(uint4*)(u1r + 4) = ub;
                *(uint4*)(u1r + 8) = uc; *(uint4*)(u1r + 12) = ud;
            }
            gemm_pipe<4, 1, 2>(wp1w, sbase + SM_X0 + xpat, lane, acc, an);
            wpre<16, 2>(wp2w, lane, an);
            if (s != 1) epi_l1(acc, u1r, xas, biash, w, lane);
            else        epi_fwd(acc, xas, biash, w, lane);
            __syncthreads();

            if (s != 1) {
                gemm_pipe<16, 2, 2>(wp2w, sbase + SM_XA + xpat, lane, acc, an);
                wpre<16, 2>(wp3w, lane, an);
                epi_hidden<false>(acc, xbs, biash + 256, w, lane, vreg, red);
                __syncthreads();
                gemm_pipe<16, 2, 2>(wp3w, sbase + SM_XB + xpat, lane, acc, an);
                if (w < 4) wpre<16, 1>(wp4w, lane, an);
                epi_hidden<true>(acc, xas, biash + 512, w, lane, vreg, red);
                __syncthreads();
            } else {
                gemm_pipe<16, 1, 2>(wp2w, sbase + SM_XA + xpat, lane, acc, an);
                wpre<16, 2>(wp3w, lane, an);
                epi_fwd(acc, xbs, biash + 256, w, lane);
                __syncthreads();
                gemm_pipe<16, 1, 2>(wp3w, sbase + SM_XB + xpat, lane, acc, an);
                if (w < 4) wpre<16, 1>(wp4w, lane, an);
                epi_fwd(acc, xas, biash + 512, w, lane);
                __syncthreads();
            }

            // L4: forward-only on warps 0..3 (16 rows each); epilogue folds RK inline
            if (w < 4) {
                gemm_pipe<16, 1, 1>(wp4w, sbase + SM_XA + xpat, lane, acc, an);
            }
            wpre<4, 2>(wp1w, lane, an);
            if (w < 4) {
                int g = lane >> 2, j2 = (lane & 3) * 2;
                int d0 = w * 16 + g;
                float bb0 = __half2float(b4h[d0]), bb8 = __half2float(b4h[d0 + 8]);
                float cs = (s < 5) ? c_HA[s + 1][s] : c_HB[5];
#pragma unroll
                for (int nb = 0; nb < 4; nb++) {
                    float2 c01 = __half22float2(*(const __half2*)(acc + nb * 2));
                    float2 c23 = __half22float2(*(const __half2*)(acc + nb * 2 + 1));
                    int m = nb * 8 + j2;
                    float v00 = c01.x + bb0, v01 = c01.y + bb0;
                    float v10 = c23.x + bb8, v11 = c23.y + bb8;
                    float x00 = zb[d0 * ZBP + m],       x01 = zb[d0 * ZBP + m + 1];
                    float x10 = zb[(d0 + 8) * ZBP + m], x11 = zb[(d0 + 8) * ZBP + m + 1];
                    if (s < 5) {
                        *(__half2*)(kdzh + s * KDZS + d0 * KDZP + m)       = __floats2half2_rn(v00, v01);
                        *(__half2*)(kdzh + s * KDZS + (d0 + 8) * KDZP + m) = __floats2half2_rn(v10, v11);
                        for (int j = 0; j < s; j++) {
                            float a = c_HA[s + 1][j];
                            float2 k0 = __half22float2(*(const __half2*)(kdzh + j * KDZS + d0 * KDZP + m));
                            float2 k8 = __half22float2(*(const __half2*)(kdzh + j * KDZS + (d0 + 8) * KDZP + m));
                            x00 += a * k0.x; x01 += a * k0.y;
                            x10 += a * k8.x; x11 += a * k8.y;
                        }
                    } else {
#pragma unroll
                        for (int j = 0; j < 5; j++) {
                            if (j == 1) continue;
                            float bbj = c_HB[j];
                            float2 k0 = __half22float2(*(const __half2*)(kdzh + j * KDZS + d0 * KDZP + m));
                            float2 k8 = __half22float2(*(const __half2*)(kdzh + j * KDZS + (d0 + 8) * KDZP + m));
                            x00 += bbj * k0.x; x01 += bbj * k0.y;
                            x10 += bbj * k8.x; x11 += bbj * k8.y;
                        }
                    }
                    x00 += cs * v00; x01 += cs * v01;
                    x10 += cs * v10; x11 += cs * v11;
                    if (s == 5) {
                        zb[d0 * ZBP + m]           = x00;
                        zb[d0 * ZBP + m + 1]       = x01;
                        zb[(d0 + 8) * ZBP + m]     = x10;
                        zb[(d0 + 8) * ZBP + m + 1] = x11;
                    }
                    *(__half2*)(x0s + d0 * XLD + m * 2)       = __floats2half2_rn(x00, x01);
                    *(__half2*)(x0s + (d0 + 8) * XLD + m * 2) = __floats2half2_rn(x10, x11);
                }
            }
            pend = c_HB[s];
            __syncthreads();
        }
    }

    if (pend != 0.f && tid < 32)
        lpT[tid] -= pend * (red[tid] + red[32 + tid] + red[64 + tid] + red[96 + tid]
                          + red[128 + tid] + red[160 + tid] + red[192 + tid] + red[224 + tid]);
    __syncthreads();

    float* scratch = (float*)xas;
    {
        int m = tid & 31, g8 = tid >> 5;
        float p = 0.f;
#pragma unroll
        for (int dd = 0; dd < 8; dd++) {
            float z = zb[(g8 * 8 + dd) * ZBP + m];
            p -= 0.5f * z * z;
        }
        scratch[g8 * 32 + m] = p;
    }
    __syncthreads();
    if (tid < 32) {
        float sum = 0.f;
#pragma unroll
        for (int g8 = 0; g8 < 8; g8++) sum += scratch[g8 * 32 + tid];
        sum -= 32.f * 1.8378770664093453f;
        out[mbase + tid] = sum - lpT[tid];
    }
}

extern "C" void kernel_launch(void* const* d_in, const int* in_sizes, int n_in,
                              void* d_out, int out_size)
{
    const float* x   = (const float*)d_in[0];
    const float* eps = (const float*)d_in[1];
    const float* W1  = (const float*)d_in[2];
    const float* b1  = (const float*)d_in[3];
    const float* W2  = (const float*)d_in[4];
    const float* b2  = (const float*)d_in[5];
    const float* W3  = (const float*)d_in[6];
    const float* b3  = (const float*)d_in[7];
    const float* W4  = (const float*)d_in[8];
    const float* b4  = (const float*)d_in[9];
    float* out = (float*)d_out;

    prep_kernel<<<(704 * 32 + 255) / 256, 256>>>(W1, W2, W3, W4);

    cudaFuncSetAttribute(cnf_kernel, cudaFuncAttributeMaxDynamicSharedMemorySize, SM_TOTAL);
    cnf_kernel<<<32768 / TM, NTHREADS, SM_TOTAL>>>(x, eps, b1, b2, b3, b4, out);
}

// round 15
// speedup vs baseline: 1.0411x; 1.0411x over previous
#include <cuda_runtime.h>
#include <cuda_fp16.h>
#include <cstdint>

#define NTHREADS 256
#define TM 32

__constant__ float c_HA[6][5] = {
    {0.f, 0.f, 0.f, 0.f, 0.f},
    {0.05f, 0.f, 0.f, 0.f, 0.f},
    {0.01875f, 0.05625f, 0.f, 0.f, 0.f},
    {0.24444444444444444f, -0.93333333333333333f, 0.88888888888888888f, 0.f, 0.f},
    {0.73814967232162782f, -2.89894833155005335f, 2.45572321290182902f, -0.07270233196159122f, 0.f},
    {0.71156881313131313f, -2.68939393939393939f, 2.22660567943586826f, 0.06960227272727273f, -0.06838282589193830f}
};
__constant__ float c_HB[6] = {
    0.02278645833333333f, 0.f, 0.11230907457322552f,
    0.16276041666666666f, -0.08059404481132076f, 0.03273809523809524f
};

__device__ __align__(16) __half g_Wp1[256 * 64];
__device__ __align__(16) __half g_Wp2[256 * 256];
__device__ __align__(16) __half g_Wp3[256 * 256];
__device__ __align__(16) __half g_Wp4[64 * 256];
__device__ __align__(16) __half g_Wp4t[256 * 64];         // W4^T (for V = W4^T eps)
__device__ __align__(16) uint32_t g_U1[1024 * 256 * 16];  // per-(cta,warp,lane) U1 frags

// ---- SMEM layout ----
#define XLD 144
#define SM_XA    0              // [256][72h] = 36864
#define SM_XB    36864          // [256][72h]; rows 0..63 double as X0 (fwd only)
#define SM_X0    SM_XB
#define SM_KDZ   73728          // fp16 [5][64][34] = 21760
#define SM_ZB    95488          // f32 [64][33] = 8448
#define SM_EP    103936         // fp16 [64][34] = 4352
#define SM_BIAS  108288         // fp16 832 -> 1664
#define SM_RED   109952         // f32 [8][32] = 1024
#define SM_LPT   110976         // f32 [32] = 128
#define SM_TOTAL 111104

#define KDZP 34
#define KDZS 2176
#define ZBP  33
#define EPP  34

__device__ __forceinline__ uint32_t smem_u32(const void* p) {
    uint32_t a;
    asm("{ .reg .u64 t; cvta.to.shared.u64 t, %1; cvt.u32.u64 %0, t; }" : "=r"(a) : "l"(p));
    return a;
}
__device__ __forceinline__ void ldsm4t(uint32_t addr, uint32_t& r0, uint32_t& r1,
                                       uint32_t& r2, uint32_t& r3) {
    asm volatile("ldmatrix.sync.aligned.m8n8.x4.trans.shared.b16 {%0,%1,%2,%3}, [%4];"
                 : "=r"(r0), "=r"(r1), "=r"(r2), "=r"(r3) : "r"(addr));
}
__device__ __forceinline__ void mma16816h(uint32_t* c, const uint4& a, uint32_t b0, uint32_t b1) {
    asm volatile("mma.sync.aligned.m16n8k16.row.col.f16.f16.f16.f16 "
                 "{%0,%1}, {%2,%3,%4,%5}, {%6,%7}, {%0,%1};"
                 : "+r"(c[0]), "+r"(c[1])
                 : "r"(a.x), "r"(a.y), "r"(a.z), "r"(a.w), "r"(b0), "r"(b1));
}
__device__ __forceinline__ float tanh_fast(float x) {
    float e;
    asm("ex2.approx.f32 %0, %1;" : "=f"(e) : "f"(x * 2.8853900817779268f));
    float q = e + 1.0f;
    float r = __int_as_float(0x7EF311C3 - __float_as_int(q));
    r = r * fmaf(-q, r, 2.f);
    r = r * fmaf(-q, r, 2.f);
    return fmaf(-2.0f, r, 1.0f);
}
// packed tangent scale: (1 - y*y) * u, all in half2
__device__ __forceinline__ uint32_t tangent_h2(uint32_t yh2, uint32_t uh2) {
    __half2 y = *(__half2*)&yh2;
    __half2 u = *(__half2*)&uh2;
    __half2 one = __floats2half2_rn(1.f, 1.f);
    __half2 s = __hfma2(__hneg2(y), y, one);
    __half2 t = __hmul2(s, u);
    return *(uint32_t*)&t;
}

// ---- prep: pack fp32 weights into fp16 fragment-major layouts ----
__global__ void prep_kernel(const float* __restrict__ W1, const float* __restrict__ W2,
                            const float* __restrict__ W3, const float* __restrict__ W4)
{
    int t = blockIdx.x * blockDim.x + threadIdx.x;
    if (t >= 704 * 32) return;
    int frag = t >> 5, lane = t & 31;
    int g = lane >> 2, j2 = (lane & 3) * 2;
    __half h[8];
    if (frag >= 640) {               // W4^T: [256][64]
        int fl = frag - 640;
        int mt = fl >> 2, ks = fl & 3;
        int r0 = mt * 16 + g, r1 = r0 + 8;
        int c0 = ks * 16 + j2;
        h[0] = __float2half_rn(W4[(c0)     * 256 + r0]);
        h[1] = __float2half_rn(W4[(c0 + 1) * 256 + r0]);
        h[2] = __float2half_rn(W4[(c0)     * 256 + r1]);
        h[3] = __float2half_rn(W4[(c0 + 1) * 256 + r1]);
        h[4] = __float2half_rn(W4[(c0 + 8) * 256 + r0]);
        h[5] = __float2half_rn(W4[(c0 + 9) * 256 + r0]);
        h[6] = __float2half_rn(W4[(c0 + 8) * 256 + r1]);
        h[7] = __float2half_rn(W4[(c0 + 9) * 256 + r1]);
        *(uint4*)(g_Wp4t + fl * 256 + lane * 8) = *(uint4*)h;
        return;
    }
    const float* W; __half* dst; int ksn, ld, fl;
    if (frag < 64)       { W = W1; dst = g_Wp1; ksn = 4;  ld = 64;  fl = frag; }
    else if (frag < 320) { W = W2; dst = g_Wp2; ksn = 16; ld = 256; fl = frag - 64; }
    else if (frag < 576) { W = W3; dst = g_Wp3; ksn = 16; ld = 256; fl = frag - 320; }
    else                 { W = W4; dst = g_Wp4; ksn = 16; ld = 256; fl = frag - 576; }
    int mt = fl / ksn, ks = fl % ksn;
    int r0 = mt * 16 + g, r1 = r0 + 8;
    int c0 = ks * 16 + j2;
    h[0] = __float2half_rn(W[r0 * ld + c0]);
    h[1] = __float2half_rn(W[r0 * ld + c0 + 1]);
    h[2] = __float2half_rn(W[r1 * ld + c0]);
    h[3] = __float2half_rn(W[r1 * ld + c0 + 1]);
    h[4] = __float2half_rn(W[r0 * ld + c0 + 8]);
    h[5] = __float2half_rn(W[r0 * ld + c0 + 9]);
    h[6] = __float2half_rn(W[r1 * ld + c0 + 8]);
    h[7] = __float2half_rn(W[r1 * ld + c0 + 9]);
    *(uint4*)(dst + fl * 256 + lane * 8) = *(uint4*)h;
}

template<int KSTEPS, int MT>
__device__ __forceinline__ void wpre(const uint4* __restrict__ wf, int lane, uint4* an)
{
#pragma unroll
    for (int mt = 0; mt < MT; mt++) {
        an[mt]      = wf[mt * KSTEPS * 32 + lane];
        an[MT + mt] = wf[(mt * KSTEPS + 1) * 32 + lane];
    }
}

// ---- software-pipelined tensor-core GEMM (fp16 acc) ----
template<int KSTEPS, int NPH, int MT>
__device__ __forceinline__ void gemm_pipe(const uint4* __restrict__ wf,
                                          uint32_t xaddr, int lane,
                                          uint32_t* acc, uint4* an)
{
#pragma unroll
    for (int i = 0; i < MT * NPH * 8; i++) acc[i] = 0u;
    uint32_t bb[2][8];
    ldsm4t(xaddr,      bb[0][0], bb[0][1], bb[0][2], bb[0][3]);
    ldsm4t(xaddr + 32, bb[0][4], bb[0][5], bb[0][6], bb[0][7]);
    int par = 0;
#pragma unroll
    for (int ks = 0; ks < KSTEPS; ks++) {
        uint4 ac[MT];
#pragma unroll
        for (int mt = 0; mt < MT; mt++) ac[mt] = an[(ks & 1) * MT + mt];
        if (ks + 2 < KSTEPS) {
#pragma unroll
            for (int mt = 0; mt < MT; mt++)
                an[(ks & 1) * MT + mt] = wf[(mt * KSTEPS + ks + 2) * 32 + lane];
        }
#pragma unroll
        for (int h = 0; h < NPH; h++) {
            int nh = h + 1, nks = ks;
            if (nh == NPH) { nh = 0; nks = ks + 1; }
            if (nks < KSTEPS) {
                uint32_t a2 = xaddr + nks * (16 * XLD) + nh * 64;
                ldsm4t(a2,      bb[par ^ 1][0], bb[par ^ 1][1], bb[par ^ 1][2], bb[par ^ 1][3]);
                ldsm4t(a2 + 32, bb[par ^ 1][4], bb[par ^ 1][5], bb[par ^ 1][6], bb[par ^ 1][7]);
            }
            const uint32_t* B = bb[par];
#pragma unroll
            for (int mt = 0; mt < MT; mt++) {
                uint32_t* am = acc + mt * NPH * 8 + 8 * h;
                mma16816h(am + 0, ac[mt], B[0], B[1]);
                mma16816h(am + 2, ac[mt], B[2], B[3]);
                mma16816h(am + 4, ac[mt], B[4], B[5]);
                mma16816h(am + 6, ac[mt], B[6], B[7]);
            }
            par ^= 1;
        }
    }
}

// ---- L1 epilogue: fwd acc + cached U1 -> tanh + packed tangent -> XA ----
__device__ __forceinline__ void epi_l1(const uint32_t* acc, const uint32_t* u1r,
                                       char* xout, const __half* bias, int w, int lane)
{
    int g = lane >> 2, j2 = (lane & 3) * 2;
#pragma unroll
    for (int mt = 0; mt < 2; mt++) {
        int r = w * 32 + mt * 16 + g;
        float b0 = __half2float(bias[r]), b8 = __half2float(bias[r + 8]);
        char* row0 = xout + r * XLD;
        char* row8 = row0 + 8 * XLD;
#pragma unroll
        for (int nb = 0; nb < 4; nb++) {
            float2 c01 = __half22float2(*(const __half2*)(acc + mt * 8 + 2 * nb));
            float2 c23 = __half22float2(*(const __half2*)(acc + mt * 8 + 2 * nb + 1));
            int n2 = (nb * 8 + j2) * 2;
            float y0 = tanh_fast(c01.x + b0), y1 = tanh_fast(c01.y + b0);
            float y2 = tanh_fast(c23.x + b8), y3 = tanh_fast(c23.y + b8);
            __half2 yh01 = __floats2half2_rn(y0, y1);
            __half2 yh23 = __floats2half2_rn(y2, y3);
            *(__half2*)(row0 + n2) = yh01;
            *(__half2*)(row8 + n2) = yh23;
            *(uint32_t*)(row0 + 64 + n2) = tangent_h2(*(uint32_t*)&yh01, u1r[mt * 8 + 2 * nb]);
            *(uint32_t*)(row8 + 64 + n2) = tangent_h2(*(uint32_t*)&yh23, u1r[mt * 8 + 2 * nb + 1]);
        }
    }
}

// ---- hidden epilogue (NPH=2, MT=2). DIV: fold divergence via V regs ----
template<bool DIV>
__device__ __forceinline__ void epi_hidden(const uint32_t* acc, char* xout,
                                           const __half* bias, int w, int lane,
                                           const uint32_t* vreg, float* red)
{
    int g = lane >> 2, j2 = (lane & 3) * 2;
    float ds0[4], ds1[4];
    if (DIV) {
#pragma unroll
        for (int nb = 0; nb < 4; nb++) { ds0[nb] = 0.f; ds1[nb] = 0.f; }
    }
#pragma unroll
    for (int mt = 0; mt < 2; mt++) {
        int r = w * 32 + mt * 16 + g;
        float b0 = __half2float(bias[r]), b8 = __half2float(bias[r + 8]);
        char* row0 = xout + r * XLD;
        char* row8 = row0 + 8 * XLD;
#pragma unroll
        for (int nb = 0; nb < 4; nb++) {
            float2 cf01 = __half22float2(*(const __half2*)(acc + mt * 16 + 2 * nb));
            float2 cf23 = __half22float2(*(const __half2*)(acc + mt * 16 + 2 * nb + 1));
            int n2 = (nb * 8 + j2) * 2;
            float y0 = tanh_fast(cf01.x + b0), y1 = tanh_fast(cf01.y + b0);
            float y2 = tanh_fast(cf23.x + b8), y3 = tanh_fast(cf23.y + b8);
            __half2 yh01 = __floats2half2_rn(y0, y1);
            __half2 yh23 = __floats2half2_rn(y2, y3);
            *(__half2*)(row0 + n2) = yh01;
            *(__half2*)(row8 + n2) = yh23;
            uint32_t t01 = tangent_h2(*(uint32_t*)&yh01, acc[mt * 16 + 8 + 2 * nb]);
            uint32_t t23 = tangent_h2(*(uint32_t*)&yh23, acc[mt * 16 + 8 + 2 * nb + 1]);
            *(uint32_t*)(row0 + 64 + n2) = t01;
            *(uint32_t*)(row8 + 64 + n2) = t23;
            if (DIV) {
                float2 tf01 = __half22float2(*(__half2*)&t01);
                float2 tf23 = __half22float2(*(__half2*)&t23);
                float2 v01 = __half22float2(*(const __half2*)(vreg + mt * 8 + 2 * nb));
                float2 v23 = __half22float2(*(const __half2*)(vreg + mt * 8 + 2 * nb + 1));
                ds0[nb] += tf01.x * v01.x + tf23.x * v23.x;
                ds1[nb] += tf01.y * v01.y + tf23.y * v23.y;
            }
        }
    }
    if (DIV) {
#pragma unroll
        for (int mask = 4; mask <= 16; mask <<= 1) {
#pragma unroll
            for (int nb = 0; nb < 4; nb++) {
                ds0[nb] += __shfl_xor_sync(0xffffffffu, ds0[nb], mask);
                ds1[nb] += __shfl_xor_sync(0xffffffffu, ds1[nb], mask);
            }
        }
        if (g == 0) {
#pragma unroll
            for (int nb = 0; nb < 4; nb++) {
                red[w * 32 + nb * 8 + j2]     = ds0[nb];
                red[w * 32 + nb * 8 + j2 + 1] = ds1[nb];
            }
        }
    }
}

// ---- forward-only epilogue (NPH=1), for s==1 ----
__device__ __forceinline__ void epi_fwd(const uint32_t* acc, char* xout,
                                        const __half* bias, int w, int lane)
{
    int g = lane >> 2, j2 = (lane & 3) * 2;
#pragma unroll
    for (int mt = 0; mt < 2; mt++) {
        int r = w * 32 + mt * 16 + g;
        float b0 = __half2float(bias[r]), b8 = __half2float(bias[r + 8]);
        char* row0 = xout + r * XLD;
        char* row8 = row0 + 8 * XLD;
#pragma unroll
        for (int nb = 0; nb < 4; nb++) {
            float2 c01 = __half22float2(*(const __half2*)(acc + mt * 8 + 2 * nb));
            float2 c23 = __half22float2(*(const __half2*)(acc + mt * 8 + 2 * nb + 1));
            int n2 = (nb * 8 + j2) * 2;
            float y0 = tanh_fast(c01.x + b0), y1 = tanh_fast(c01.y + b0);
            float y2 = tanh_fast(c23.x + b8), y3 = tanh_fast(c23.y + b8);
            *(__half2*)(row0 + n2) = __floats2half2_rn(y0, y1);
            *(__half2*)(row8 + n2) = __floats2half2_rn(y2, y3);
        }
    }
}

__global__ void __launch_bounds__(NTHREADS, 2)
cnf_kernel(const float* __restrict__ x, const float* __restrict__ eps,
           const float* __restrict__ b1, const float* __restrict__ b2,
           const float* __restrict__ b3, const float* __restrict__ b4,
           float* __restrict__ out)
{
    extern __shared__ char smc[];
    const uint32_t sbase = smem_u32(smc);
    const int tid = threadIdx.x;
    const int w = tid >> 5;
    const int lane = tid & 31;
    const int mbase = blockIdx.x * TM;

    __half* biash = (__half*)(smc + SM_BIAS);
    char*   x0s   = smc + SM_X0;
    char*   xas   = smc + SM_XA;
    char*   xbs   = smc + SM_XB;
    __half* kdzh  = (__half*)(smc + SM_KDZ);
    float*  zb    = (float*)(smc + SM_ZB);
    __half* eph   = (__half*)(smc + SM_EP);
    float*  red   = (float*)(smc + SM_RED);
    float*  lpT   = (float*)(smc + SM_LPT);
    const __half* b4h = biash + 768;

    const uint4* wp1w  = (const uint4*)g_Wp1  + (w * 2 * 4) * 32;
    const uint4* wp2w  = (const uint4*)g_Wp2  + (w * 2 * 16) * 32;
    const uint4* wp3w  = (const uint4*)g_Wp3  + (w * 2 * 16) * 32;
    const uint4* wp4w  = (const uint4*)g_Wp4  + ((w & 3) * 16) * 32;
    const uint4* wp4tw = (const uint4*)g_Wp4t + (w * 2 * 4) * 32;
    uint4* u1gp = (uint4*)(g_U1 + ((size_t)(blockIdx.x * 8 + w) * 32 + lane) * 16);

    biash[tid]       = __float2half_rn(b1[tid]);
    biash[256 + tid] = __float2half_rn(b2[tid]);
    biash[512 + tid] = __float2half_rn(b3[tid]);
    if (tid < 64) biash[768 + tid] = __float2half_rn(b4[tid]);
    for (int e = tid; e < 64 * TM; e += NTHREADS) {
        int d = e & 63, m = e >> 6;
        float xv = x[(mbase + m) * 64 + d];
        float ev = eps[(mbase + m) * 64 + d];
        __half evh = __float2half_rn(ev);
        zb[d * ZBP + m]  = xv;
        eph[d * EPP + m] = evh;
        *(__half*)(x0s + d * XLD + m * 2) = __float2half_rn(xv);
        *(__half*)(xas + d * XLD + m * 2) = evh;   // eps tile for V / U1 gemms
    }
    if (tid < TM) lpT[tid] = 0.f;
    __syncthreads();

    const uint32_t xpat = ((lane & 7) + ((lane >> 3) & 1) * 8) * XLD + (lane >> 4) * 16;

    // V = W4^T eps (divergence trick) and U1 = W1 eps (stage-constant L1 tangent)
    uint4 an[4];
    uint32_t vreg[16];
    wpre<4, 2>(wp4tw, lane, an);
    gemm_pipe<4, 1, 2>(wp4tw, sbase + SM_XA + xpat, lane, vreg, an);
    {
        uint32_t u1r[16];
        wpre<4, 2>(wp1w, lane, an);
        gemm_pipe<4, 1, 2>(wp1w, sbase + SM_XA + xpat, lane, u1r, an);
        u1gp[0] = *(uint4*)(u1r + 0);
        u1gp[1] = *(uint4*)(u1r + 4);
        u1gp[2] = *(uint4*)(u1r + 8);
        u1gp[3] = *(uint4*)(u1r + 12);
    }
    wpre<4, 2>(wp1w, lane, an);
    __syncthreads();

    uint32_t acc[32];
    float pend = 0.f;

#pragma unroll 1
    for (int step = 0; step < 4; step++) {
#pragma unroll 1
        for (int s = 0; s < 6; s++) {
            if (pend != 0.f && tid < 32)
                lpT[tid] -= pend * (red[tid] + red[32 + tid] + red[64 + tid] + red[96 + tid]
                                  + red[128 + tid] + red[160 + tid] + red[192 + tid] + red[224 + tid]);

            // L1: forward-only, tangent from cached U1
            uint32_t u1r[16];
            if (s != 1) {
                uint4 ua = u1gp[0], ub = u1gp[1], uc = u1gp[2], ud = u1gp[3];
                *(uint4*)(u1r + 0) = ua; *(uint4*)(u1r + 4) = ub;
                *(uint4*)(u1r + 8) = uc; *(uint4*)(u1r + 12) = ud;
            }
            gemm_pipe<4, 1, 2>(wp1w, sbase + SM_X0 + xpat, lane, acc, an);
            wpre<16, 2>(wp2w, lane, an);
            if (s != 1) epi_l1(acc, u1r, xas, biash, w, lane);
            else        epi_fwd(acc, xas, biash, w, lane);
            __syncthreads();

            if (s != 1) {
                gemm_pipe<16, 2, 2>(wp2w, sbase + SM_XA + xpat, lane, acc, an);
                wpre<16, 2>(wp3w, lane, an);
                epi_hidden<false>(acc, xbs, biash + 256, w, lane, vreg, red);
                __syncthreads();
                gemm_pipe<16, 2, 2>(wp3w, sbase + SM_XB + xpat, lane, acc, an);
                if (w < 4) wpre<16, 1>(wp4w, lane, an);
                epi_hidden<true>(acc, xas, biash + 512, w, lane, vreg, red);
                __syncthreads();
            } else {
                gemm_pipe<16, 1, 2>(wp2w, sbase + SM_XA + xpat, lane, acc, an);
                wpre<16, 2>(wp3w, lane, an);
                epi_fwd(acc, xbs, biash + 256, w, lane);
                __syncthreads();
                gemm_pipe<16, 1, 2>(wp3w, sbase + SM_XB + xpat, lane, acc, an);
                if (w < 4) wpre<16, 1>(wp4w, lane, an);
                epi_fwd(acc, xas, biash + 512, w, lane);
                __syncthreads();
            }

            // L4: forward-only on warps 0..3 (16 rows each); epilogue folds RK inline
            if (w < 4) {
                gemm_pipe<16, 1, 1>(wp4w, sbase + SM_XA + xpat, lane, acc, an);
            }
            wpre<4, 2>(wp1w, lane, an);
            if (w < 4) {
                int g = lane >> 2, j2 = (lane & 3) * 2;
                int d0 = w * 16 + g;
                float bb0 = __half2float(b4h[d0]), bb8 = __half2float(b4h[d0 + 8]);
                float cs = (s < 5) ? c_HA[s + 1][s] : c_HB[5];
#pragma unroll
                for (int nb = 0; nb < 4; nb++) {
                    float2 c01 = __half22float2(*(const __half2*)(acc + nb * 2));
                    float2 c23 = __half22float2(*(const __half2*)(acc + nb * 2 + 1));
                    int m = nb * 8 + j2;
                    float v00 = c01.x + bb0, v01 = c01.y + bb0;
                    float v10 = c23.x + bb8, v11 = c23.y + bb8;
                    float x00 = zb[d0 * ZBP + m],       x01 = zb[d0 * ZBP + m + 1];
                    float x10 = zb[(d0 + 8) * ZBP + m], x11 = zb[(d0 + 8) * ZBP + m + 1];
                    if (s < 5) {
                        *(__half2*)(kdzh + s * KDZS + d0 * KDZP + m)       = __floats2half2_rn(v00, v01);
                        *(__half2*)(kdzh + s * KDZS + (d0 + 8) * KDZP + m) = __floats2half2_rn(v10, v11);
                        for (int j = 0; j < s; j++) {
                            float a = c_HA[s + 1][j];
                            float2 k0 = __half22float2(*(const __half2*)(kdzh + j * KDZS + d0 * KDZP + m));
                            float2 k8 = __half22float2(*(const __half2*)(kdzh + j * KDZS + (d0 + 8) * KDZP + m));
                            x00 += a * k0.x; x01 += a * k0.y;
                            x10 += a * k8.x; x11 += a * k8.y;
                        }
                    } else {
#pragma unroll
                        for (int j = 0; j < 5; j++) {
                            if (j == 1) continue;
                            float bbj = c_HB[j];
                            float2 k0 = __half22float2(*(const __half2*)(kdzh + j * KDZS + d0 * KDZP + m));
                            float2 k8 = __half22float2(*(const __half2*)(kdzh + j * KDZS + (d0 + 8) * KDZP + m));
                            x00 += bbj * k0.x; x01 += bbj * k0.y;
                            x10 += bbj * k8.x; x11 += bbj * k8.y;
                        }
                    }
                    x00 += cs * v00; x01 += cs * v01;
                    x10 += cs * v10; x11 += cs * v11;
                    if (s == 5) {
                        zb[d0 * ZBP + m]           = x00;
                        zb[d0 * ZBP + m + 1]       = x01;
                        zb[(d0 + 8) * ZBP + m]     = x10;
                        zb[(d0 + 8) * ZBP + m + 1] = x11;
                    }
                    *(__half2*)(x0s + d0 * XLD + m * 2)       = __floats2half2_rn(x00, x01);
                    *(__half2*)(x0s + (d0 + 8) * XLD + m * 2) = __floats2half2_rn(x10, x11);
                }
            }
            pend = c_HB[s];
            __syncthreads();
        }
    }

    if (pend != 0.f && tid < 32)
        lpT[tid] -= pend * (red[tid] + red[32 + tid] + red[64 + tid] + red[96 + tid]
                          + red[128 + tid] + red[160 + tid] + red[192 + tid] + red[224 + tid]);
    __syncthreads();

    float* scratch = (float*)xas;
    {
        int m = tid & 31, g8 = tid >> 5;
        float p = 0.f;
#pragma unroll
        for (int dd = 0; dd < 8; dd++) {
            float z = zb[(g8 * 8 + dd) * ZBP + m];
            p -= 0.5f * z * z;
        }
        scratch[g8 * 32 + m] = p;
    }
    __syncthreads();
    if (tid < 32) {
        float sum = 0.f;
#pragma unroll
        for (int g8 = 0; g8 < 8; g8++) sum += scratch[g8 * 32 + tid];
        sum -= 32.f * 1.8378770664093453f;
        out[mbase + tid] = sum - lpT[tid];
    }
}

extern "C" void kernel_launch(void* const* d_in, const int* in_sizes, int n_in,
                              void* d_out, int out_size)
{
    const float* x   = (const float*)d_in[0];
    const float* eps = (const float*)d_in[1];
    const float* W1  = (const float*)d_in[2];
    const float* b1  = (const float*)d_in[3];
    const float* W2  = (const float*)d_in[4];
    const float* b2  = (const float*)d_in[5];
    const float* W3  = (const float*)d_in[6];
    const float* b3  = (const float*)d_in[7];
    const float* W4  = (const float*)d_in[8];
    const float* b4  = (const float*)d_in[9];
    float* out = (float*)d_out;

    prep_kernel<<<(704 * 32 + 255) / 256, 256>>>(W1, W2, W3, W4);

    cudaFuncSetAttribute(cnf_kernel, cudaFuncAttributeMaxDynamicSharedMemorySize, SM_TOTAL);
    cnf_kernel<<<32768 / TM, NTHREADS, SM_TOTAL>>>(x, eps, b1, b2, b3, b4, out);
}